// round 11
// baseline (speedup 1.0000x reference)
#include <cuda_runtime.h>
#include <cstdint>

// Problem constants
#define T_STEPS 512
#define BATCH   32
#define DIM     512
#define HID     256
#define A1N     16
#define A2N     128

typedef unsigned long long ull;

// ---------------- device scratch (allocation-free rule: __device__ globals) ----
__device__ float g_lut[8200];                    // exp(f(x)) lookup table
__device__ float g_seq[T_STEPS * BATCH];         // stage-1 output (T,B)
__device__ float g_hs [T_STEPS * BATCH * HID];   // LSTM hidden history (T,B,H)
__device__ float g_s2 [T_STEPS * BATCH];         // stage-3 logits (T,B)

// =============================================================================
// K0: build LUT  g(x) = exp( sum_a u1[a] * tanh(x*W1[a] + b1[a]) ),  x in [-8,8]
// =============================================================================
__global__ void k0_lut(const float* __restrict__ W1,
                       const float* __restrict__ b1,
                       const float* __restrict__ u1) {
    int i = blockIdx.x * blockDim.x + threadIdx.x;
    if (i > 8192) return;
    float x = -8.f + (float)i * (16.f / 8192.f);
    float f = 0.f;
#pragma unroll
    for (int a = 0; a < A1N; a++)
        f += u1[a] * tanhf(x * W1[a] + b1[a]);
    g_lut[i] = expf(f);
}

// =============================================================================
// K1: AttLayer1 soft pool over D.  seq[t,b] = sum_d x*g(x) / sum_d g(x)
// =============================================================================
__global__ __launch_bounds__(256) void k1_att1(const float* __restrict__ x) {
    __shared__ float lut[8193];
    for (int i = threadIdx.x; i < 8193; i += 256) lut[i] = g_lut[i];
    __syncthreads();

    int warp = threadIdx.x >> 5, lane = threadIdx.x & 31;
#pragma unroll
    for (int q = 0; q < 4; q++) {
        int pair = blockIdx.x * 32 + warp * 4 + q;     // pair = t*B + b
        const float* xp = x + (size_t)pair * DIM;
        float aw = 0.f, axw = 0.f;
#pragma unroll 4
        for (int d = lane; d < DIM; d += 32) {
            float v = xp[d];
            float pos = (v + 8.f) * 512.f;
            pos = fminf(fmaxf(pos, 0.f), 8191.0f);
            int   i0 = (int)pos;
            float fr = pos - (float)i0;
            float g0 = lut[i0], g1 = lut[i0 + 1];
            float g  = g0 + fr * (g1 - g0);
            aw  += g;
            axw += v * g;
        }
#pragma unroll
        for (int o = 16; o > 0; o >>= 1) {
            aw  += __shfl_xor_sync(0xFFFFFFFFu, aw,  o);
            axw += __shfl_xor_sync(0xFFFFFFFFu, axw, o);
        }
        if (lane == 0) g_seq[pair] = axw / aw;
    }
}

// =============================================================================
// K_NOP: profiling-slot alignment dummy (keeps ncu capture slot on k2)
// =============================================================================
__global__ void k_nop() {}

// =============================================================================
// K2: LSTM recurrence.  8 clusters x 8 CTAs, 4 batches/cluster in FOUR groups
// of ONE batch each -- 4 independent sync/flight chains per step so each
// group's DSMEM latency hides under the other groups' GEMV work.
// Block = 288: warps 0-7 GEMV+activation (broadcast LDS, l=tid&127, kh=tid>>7),
// warp 8 = c-update + DSMEM push.
// =============================================================================
__device__ __forceinline__ unsigned smem_u32(const void* p) {
    unsigned a;
    asm("{ .reg .u64 t; cvta.to.shared.u64 t, %1; cvt.u32.u64 %0, t; }"
        : "=r"(a) : "l"(p));
    return a;
}

__device__ __forceinline__ float fsigmoid(float x) {
    return __fdividef(1.f, 1.f + __expf(-x));
}
__device__ __forceinline__ float ftanh(float x) {
    return __fdividef(2.f, 1.f + __expf(-2.f * x)) - 1.f;
}

__device__ __forceinline__ unsigned ld_acq_cluster(unsigned addr) {
    unsigned v;
    asm volatile("ld.acquire.cluster.shared::cta.u32 %0, [%1];"
                 : "=r"(v) : "r"(addr) : "memory");
    return v;
}

// poll all 8 source flags >= tgt  (R5/R7-proven scalar acquire loads)
__device__ __forceinline__ void poll_flags(unsigned fl_addr, unsigned tgt) {
    for (;;) {
        bool ok = true;
#pragma unroll
        for (int i = 0; i < 8; i++)
            ok &= (ld_acq_cluster(fl_addr + 4u * i) >= tgt);
        if (ok) break;
    }
}

#define NTHR 288

__global__ void __cluster_dims__(8, 1, 1) __launch_bounds__(NTHR, 1)
k2_lstm(const float* __restrict__ Whh, const float* __restrict__ Wih,
        const float* __restrict__ bih, const float* __restrict__ bhh,
        const float* __restrict__ h0,  const float* __restrict__ c0) {
    // hbuf[g][ph] = full 256-float h vector of batch b0g+g, as 128 ull k-pairs
    __shared__ ull    hbuf[4][2][128];        // 8 KB
    __shared__ float  psum[4][128];           // kh=1 partial sums, 2 KB
    __shared__ float  act [4][128];           // activated gates, 2 KB
    __shared__ float4 hloc[4][8];             // staged outgoing h (32 floats/group)
    __shared__ float  sq[4][T_STEPS];         // 8 KB
    __shared__ __align__(16) unsigned flags[4][8];

    const int tid = threadIdx.x;
    unsigned rank;
    asm("mov.u32 %0, %%cluster_ctarank;" : "=r"(rank));
    const int cid = blockIdx.x >> 3;
    const int b0g = cid * 4;

    // ---- common preloads -------------------------------------------------------
    for (int i = tid; i < 4 * T_STEPS; i += NTHR) {
        int bb = i >> 9, tt = i & 511;
        sq[bb][tt] = g_seq[tt * BATCH + b0g + bb];
    }
    for (int i = tid; i < 4 * HID; i += NTHR) {
        int g = i >> 8, U = i & 255;
        ((float*)&hbuf[g][0][0])[U] = h0[(b0g + g) * HID + U];
    }
    if (tid < 32) flags[tid >> 3][tid & 7] = 0;

    const unsigned hl_addr = smem_u32(&hloc[0][0]);
    const unsigned fl_addr = smem_u32(&flags[0][0]);

    if (tid < 256) {
        // ======================= GEMV role (warps 0-7) ==========================
        const int l  = tid & 127;           // gate row (broadcast-preserving map)
        const int kh = tid >> 7;            // k-half
        const int grow = (l >> 5) * HID + (int)rank * 32 + (l & 31);
        const bool isg = ((l >> 5) == 2);   // g-gate -> tanh

        ull w[64];
        const ull* wrow = reinterpret_cast<const ull*>(Whh) + (size_t)grow * 128 + kh * 64;
#pragma unroll
        for (int j = 0; j < 64; j++) w[j] = wrow[j];

        const float bsum = bih[grow] + bhh[grow];
        const float wih  = Wih[grow];

        __syncthreads();
        asm volatile("barrier.cluster.arrive.aligned;" ::: "memory");
        asm volatile("barrier.cluster.wait.aligned;"   ::: "memory");

        for (int t = 0; t < T_STEPS; t++) {
            const int ph = t & 1;
            const unsigned tgt = (unsigned)t;

#pragma unroll
            for (int g = 0; g < 4; g++) {
                poll_flags(fl_addr + 32u * g, tgt);
                // GEMV: dot over this thread's 128-k half for ONE batch
                const ulonglong2* hp =
                    reinterpret_cast<const ulonglong2*>(&hbuf[g][ph][kh * 64]);
                ull a0 = 0ULL, a1 = 0ULL;
#pragma unroll
                for (int j = 0; j < 32; j++) {
                    ulonglong2 h2 = hp[j];
                    asm("fma.rn.f32x2 %0, %1, %2, %0;" : "+l"(a0) : "l"(w[2 * j]),     "l"(h2.x));
                    asm("fma.rn.f32x2 %0, %1, %2, %0;" : "+l"(a1) : "l"(w[2 * j + 1]), "l"(h2.y));
                }
                float lo0, hi0, lo1, hi1;
                asm("mov.b64 {%0,%1}, %2;" : "=f"(lo0), "=f"(hi0) : "l"(a0));
                asm("mov.b64 {%0,%1}, %2;" : "=f"(lo1), "=f"(hi1) : "l"(a1));
                float s = (lo0 + hi0) + (lo1 + hi1);
                if (kh == 1) psum[g][l] = s;
                asm volatile("bar.sync %0, %1;" :: "r"(9 + g), "r"(256) : "memory");
                if (kh == 0) {
                    float sf = s + psum[g][l] + bsum + wih * sq[g][t];
                    act[g][l] = isg ? ftanh(sf) : fsigmoid(sf);
                }
                asm volatile("bar.arrive %0, %1;" :: "r"(1 + g * 2 + ph), "r"(NTHR) : "memory");
            }
        }
    } else {
        // ======================= updater role (warp 8) ==========================
        const int lane = tid - 256;                 // unit within this CTA
        const int U = (int)rank * 32 + lane;

        float c[4];
#pragma unroll
        for (int g = 0; g < 4; g++) c[g] = c0[(b0g + g) * HID + U];

        // pre-resolved remote destinations for lane<8 (peer = lane)
        unsigned dst[4][2], dfl[4];
        if (lane < 8) {
#pragma unroll
            for (int g = 0; g < 4; g++) {
#pragma unroll
                for (int p = 0; p < 2; p++) {
                    unsigned base = smem_u32(&hbuf[g][p][0]) + (unsigned)rank * 128u;
                    asm("mapa.shared::cluster.u32 %0, %1, %2;"
                        : "=r"(dst[g][p]) : "r"(base), "r"(lane));
                }
                asm("mapa.shared::cluster.u32 %0, %1, %2;"
                    : "=r"(dfl[g]) : "r"(fl_addr + 32u * g + 4u * rank), "r"(lane));
            }
        }

        __syncthreads();
        asm volatile("barrier.cluster.arrive.aligned;" ::: "memory");
        asm volatile("barrier.cluster.wait.aligned;"   ::: "memory");

        for (int t = 0; t < T_STEPS; t++) {
            const int ph = t & 1, nph = ph ^ 1;

#pragma unroll
            for (int g = 0; g < 4; g++) {
                asm volatile("bar.sync %0, %1;" :: "r"(1 + g * 2 + ph), "r"(NTHR) : "memory");
                float ai = act[g][lane],      af = act[g][32 + lane];
                float ag = act[g][64 + lane], ao = act[g][96 + lane];
                c[g] = af * c[g] + ai * ag;
                float hv = ao * ftanh(c[g]);
                ((float*)&hloc[g][0])[lane] = hv;
                __syncwarp();
                if (lane < 8) {
                    unsigned src = hl_addr + (unsigned)g * 128u;
                    unsigned d   = dst[g][nph];
#pragma unroll
                    for (int j = 0; j < 8; j++) {
                        unsigned r0, r1, r2, r3;
                        asm volatile("ld.shared.v4.b32 {%0,%1,%2,%3}, [%4];"
                                     : "=r"(r0), "=r"(r1), "=r"(r2), "=r"(r3)
                                     : "r"(src + 16u * j));
                        asm volatile("st.shared::cluster.v4.b32 [%0], {%1,%2,%3,%4};"
                                     :: "r"(d + 16u * j), "r"(r0), "r"(r1), "r"(r2), "r"(r3)
                                     : "memory");
                    }
                    asm volatile("st.release.cluster.shared::cluster.u32 [%0], %1;"
                                 :: "r"(dfl[g]), "r"((unsigned)(t + 1)) : "memory");
                }
                g_hs[((size_t)t * BATCH + b0g + g) * HID + U] = hv;
                __syncwarp();
            }
        }
    }

    // keep smem alive until all peers' in-flight remote stores complete
    asm volatile("barrier.cluster.arrive.aligned;" ::: "memory");
    asm volatile("barrier.cluster.wait.aligned;"   ::: "memory");
}

// =============================================================================
// K3: AttLayer2 logits.  s2[t,b] = sum_a u2[a]*tanh( hs[t,b,:]@W2[:,a] + b2[a] )
// =============================================================================
__global__ __launch_bounds__(256) void k3_att2(const float* __restrict__ W2,
                                               const float* __restrict__ b2,
                                               const float* __restrict__ u2) {
    __shared__ float sh[128][33];
    __shared__ float sw[32][128];
    __shared__ float sp[128][17];
    __shared__ float sb2[A2N], su2[A2N];

    const int tid = threadIdx.x;
    const int b = blockIdx.x & 31, tq = blockIdx.x >> 5;
    const int t0 = tq * 128;
    if (tid < A2N) { sb2[tid] = b2[tid]; su2[tid] = u2[tid]; }

    const int tx = tid & 15;
    const int ty = tid >> 4;

    ull acc[8][4];
#pragma unroll
    for (int i = 0; i < 8; i++)
#pragma unroll
        for (int p = 0; p < 4; p++) acc[i][p] = 0ULL;

    for (int kc = 0; kc < 8; kc++) {
        __syncthreads();
        for (int idx = tid; idx < 4096; idx += 256) {
            int tl = idx >> 5, k = idx & 31;
            sh[tl][k] = g_hs[((size_t)(t0 + tl) * BATCH + b) * HID + kc * 32 + k];
        }
        for (int idx = tid; idx < 4096; idx += 256) {
            int k = idx >> 7, a = idx & 127;
            sw[k][a] = W2[(kc * 32 + k) * A2N + a];
        }
        __syncthreads();
#pragma unroll 4
        for (int k = 0; k < 32; k++) {
            const ull* wv = reinterpret_cast<const ull*>(&sw[k][tx * 8]);
            ull w0 = wv[0], w1 = wv[1], w2_ = wv[2], w3 = wv[3];
#pragma unroll
            for (int i = 0; i < 8; i++) {
                float hvv = sh[ty * 8 + i][k];
                ull hh;
                asm("mov.b64 %0, {%1,%1};" : "=l"(hh) : "f"(hvv));
                asm("fma.rn.f32x2 %0, %1, %2, %0;" : "+l"(acc[i][0]) : "l"(w0),  "l"(hh));
                asm("fma.rn.f32x2 %0, %1, %2, %0;" : "+l"(acc[i][1]) : "l"(w1),  "l"(hh));
                asm("fma.rn.f32x2 %0, %1, %2, %0;" : "+l"(acc[i][2]) : "l"(w2_), "l"(hh));
                asm("fma.rn.f32x2 %0, %1, %2, %0;" : "+l"(acc[i][3]) : "l"(w3),  "l"(hh));
            }
        }
    }
    float sres[8];
#pragma unroll
    for (int i = 0; i < 8; i++) sres[i] = 0.f;
#pragma unroll
    for (int i = 0; i < 8; i++) {
#pragma unroll
        for (int p = 0; p < 4; p++) {
            float lo, hi;
            asm("mov.b64 {%0,%1}, %2;" : "=f"(lo), "=f"(hi) : "l"(acc[i][p]));
            int a0 = tx * 8 + p * 2;
            sres[i] += su2[a0]     * tanhf(lo + sb2[a0]);
            sres[i] += su2[a0 + 1] * tanhf(hi + sb2[a0 + 1]);
        }
    }
#pragma unroll
    for (int i = 0; i < 8; i++) sp[ty * 8 + i][tx] = sres[i];
    __syncthreads();
    if (tid < 128) {
        float s = 0.f;
#pragma unroll
        for (int xx = 0; xx < 16; xx++) s += sp[tid][xx];
        g_s2[(t0 + tid) * BATCH + b] = s;
    }
}

// =============================================================================
// K4: softmax over T, attention pool, linear head.  One CTA per batch.
// =============================================================================
__global__ __launch_bounds__(256) void k4_final(const float* __restrict__ Wl,
                                                const float* __restrict__ bl,
                                                float* __restrict__ out) {
    __shared__ float a2s[T_STEPS];
    __shared__ float red[256];
    const int b = blockIdx.x, tid = threadIdx.x;

    for (int t = tid; t < T_STEPS; t += 256)
        a2s[t] = expf(g_s2[t * BATCH + b]);
    __syncthreads();

    float p = a2s[tid] + a2s[tid + 256];
    red[tid] = p;
    __syncthreads();
#pragma unroll
    for (int o = 128; o > 0; o >>= 1) {
        if (tid < o) red[tid] += red[tid + o];
        __syncthreads();
    }
    const float inv = 1.f / red[0];
    __syncthreads();

    float acc = 0.f;
    const float* hp = g_hs + (size_t)b * HID + tid;
#pragma unroll 8
    for (int t = 0; t < T_STEPS; t++)
        acc += a2s[t] * hp[(size_t)t * BATCH * HID];
    acc *= inv;

    float v = acc * Wl[tid];
    red[tid] = v;
    __syncthreads();
#pragma unroll
    for (int o = 128; o > 0; o >>= 1) {
        if (tid < o) red[tid] += red[tid + o];
        __syncthreads();
    }
    if (tid == 0) out[b] = red[0] + bl[0];
}

// =============================================================================
// launcher
// =============================================================================
extern "C" void kernel_launch(void* const* d_in, const int* in_sizes, int n_in,
                              void* d_out, int out_size) {
    const float* inputs = (const float*)d_in[0];
    const float* W1  = (const float*)d_in[1];
    const float* b1  = (const float*)d_in[2];
    const float* u1  = (const float*)d_in[3];
    const float* Wih = (const float*)d_in[4];
    const float* Whh = (const float*)d_in[5];
    const float* bih = (const float*)d_in[6];
    const float* bhh = (const float*)d_in[7];
    const float* h0  = (const float*)d_in[8];
    const float* c0  = (const float*)d_in[9];
    const float* W2  = (const float*)d_in[10];
    const float* b2  = (const float*)d_in[11];
    const float* u2  = (const float*)d_in[12];
    const float* Wl  = (const float*)d_in[13];
    const float* bl  = (const float*)d_in[14];
    float* out = (float*)d_out;

    k0_lut  <<<33, 256>>>(W1, b1, u1);
    k1_att1 <<<512, 256>>>(inputs);
    k_nop   <<<1, 32>>>();            // keeps ncu capture slot on k2
    k2_lstm <<<64, NTHR>>>(Whh, Wih, bih, bhh, h0, c0);
    k3_att2 <<<128, 256>>>(W2, b2, u2);
    k4_final<<<32, 256>>>(Wl, bl, out);
}

// round 12
// speedup vs baseline: 1.5530x; 1.5530x over previous
#include <cuda_runtime.h>
#include <cstdint>

// Problem constants
#define T_STEPS 512
#define BATCH   32
#define DIM     512
#define HID     256
#define A1N     16
#define A2N     128

typedef unsigned long long ull;

// ---------------- device scratch (allocation-free rule: __device__ globals) ----
__device__ float g_lut[8200];                    // exp(f(x)) lookup table
__device__ float g_seq[T_STEPS * BATCH];         // stage-1 output (T,B)
__device__ float g_hs [T_STEPS * BATCH * HID];   // LSTM hidden history (T,B,H)
__device__ float g_s2 [T_STEPS * BATCH];         // stage-3 logits (T,B)

// =============================================================================
// K0: build LUT  g(x) = exp( sum_a u1[a] * tanh(x*W1[a] + b1[a]) ),  x in [-8,8]
// =============================================================================
__global__ void k0_lut(const float* __restrict__ W1,
                       const float* __restrict__ b1,
                       const float* __restrict__ u1) {
    int i = blockIdx.x * blockDim.x + threadIdx.x;
    if (i > 8192) return;
    float x = -8.f + (float)i * (16.f / 8192.f);
    float f = 0.f;
#pragma unroll
    for (int a = 0; a < A1N; a++)
        f += u1[a] * tanhf(x * W1[a] + b1[a]);
    g_lut[i] = expf(f);
}

// =============================================================================
// K1: AttLayer1 soft pool over D.  seq[t,b] = sum_d x*g(x) / sum_d g(x)
// =============================================================================
__global__ __launch_bounds__(256) void k1_att1(const float* __restrict__ x) {
    __shared__ float lut[8193];
    for (int i = threadIdx.x; i < 8193; i += 256) lut[i] = g_lut[i];
    __syncthreads();

    int warp = threadIdx.x >> 5, lane = threadIdx.x & 31;
#pragma unroll
    for (int q = 0; q < 4; q++) {
        int pair = blockIdx.x * 32 + warp * 4 + q;     // pair = t*B + b
        const float* xp = x + (size_t)pair * DIM;
        float aw = 0.f, axw = 0.f;
#pragma unroll 4
        for (int d = lane; d < DIM; d += 32) {
            float v = xp[d];
            float pos = (v + 8.f) * 512.f;
            pos = fminf(fmaxf(pos, 0.f), 8191.0f);
            int   i0 = (int)pos;
            float fr = pos - (float)i0;
            float g0 = lut[i0], g1 = lut[i0 + 1];
            float g  = g0 + fr * (g1 - g0);
            aw  += g;
            axw += v * g;
        }
#pragma unroll
        for (int o = 16; o > 0; o >>= 1) {
            aw  += __shfl_xor_sync(0xFFFFFFFFu, aw,  o);
            axw += __shfl_xor_sync(0xFFFFFFFFu, axw, o);
        }
        if (lane == 0) g_seq[pair] = axw / aw;
    }
}

// =============================================================================
// K_NOP: profiling-slot alignment dummy (keeps ncu capture slot on k2)
// =============================================================================
__global__ void k_nop() {}

// =============================================================================
// K2: LSTM recurrence.  8 clusters x 8 CTAs, 4 batches/cluster in 2 groups.
// Block = 320: warps 0-7 GEMV+activation (broadcast LDS, l=tid&127, kh=tid>>7),
// warp 8 = group-A updater, warp 9 = group-B updater (independent chains).
// Poll: 8 scalar ld.acquire (proven).  Flag ordering proof as R9.
// =============================================================================
__device__ __forceinline__ unsigned smem_u32(const void* p) {
    unsigned a;
    asm("{ .reg .u64 t; cvta.to.shared.u64 t, %1; cvt.u32.u64 %0, t; }"
        : "=r"(a) : "l"(p));
    return a;
}

__device__ __forceinline__ float fsigmoid(float x) {
    return __fdividef(1.f, 1.f + __expf(-x));
}
__device__ __forceinline__ float ftanh(float x) {
    return __fdividef(2.f, 1.f + __expf(-2.f * x)) - 1.f;
}

__device__ __forceinline__ unsigned ld_acq_cluster(unsigned addr) {
    unsigned v;
    asm volatile("ld.acquire.cluster.shared::cta.u32 %0, [%1];"
                 : "=r"(v) : "r"(addr) : "memory");
    return v;
}

// poll all 8 source flags >= tgt  (R5/R7/R9-proven scalar acquire loads)
__device__ __forceinline__ void poll_flags(unsigned fl_addr, unsigned tgt) {
    for (;;) {
        bool ok = true;
#pragma unroll
        for (int i = 0; i < 8; i++)
            ok &= (ld_acq_cluster(fl_addr + 4u * i) >= tgt);
        if (ok) break;
    }
}

// 128-k-half GEMV fragment; hp = &hbuf[ph][kh*64]
__device__ __forceinline__ void gemv128(const ulonglong2* hp, const ull* w,
                                        float& s0, float& s1) {
    ull a0 = 0ULL, a1 = 0ULL;
#pragma unroll
    for (int j = 0; j < 64; j++) {
        ulonglong2 h2 = hp[j];
        asm("fma.rn.f32x2 %0, %1, %2, %0;" : "+l"(a0) : "l"(w[j]), "l"(h2.x));
        asm("fma.rn.f32x2 %0, %1, %2, %0;" : "+l"(a1) : "l"(w[j]), "l"(h2.y));
    }
    float lo, hi;
    asm("mov.b64 {%0,%1}, %2;" : "=f"(lo), "=f"(hi) : "l"(a0));
    s0 = lo + hi;
    asm("mov.b64 {%0,%1}, %2;" : "=f"(lo), "=f"(hi) : "l"(a1));
    s1 = lo + hi;
}

#define NTHR 320
#define NACT 288   // act-ready barrier population: 8 GEMV warps + 1 updater warp

__global__ void __cluster_dims__(8, 1, 1) __launch_bounds__(NTHR, 1)
k2_lstm(const float* __restrict__ Whh, const float* __restrict__ Wih,
        const float* __restrict__ bih, const float* __restrict__ bhh,
        const float* __restrict__ h0,  const float* __restrict__ c0) {
    __shared__ float4 hbufA[2][128];          // [ph][p]: {b0[2p],b0[2p+1],b1[2p],b1[2p+1]}
    __shared__ float4 hbufB[2][128];
    __shared__ float  psumA[2][2][128][2];    // [ph][kh][row][batch]
    __shared__ float  psumB[2][2][128][2];
    __shared__ float  actA[2][128][2];        // activated gates [ph][row][batch]
    __shared__ float  actB[2][128][2];
    __shared__ float4 hlocA[16], hlocB[16];   // staged outgoing h (64 floats)
    __shared__ float  sq[4][T_STEPS];
    __shared__ __align__(16) unsigned flagsA[8], flagsB[8];

    const int tid = threadIdx.x;
    unsigned rank;
    asm("mov.u32 %0, %%cluster_ctarank;" : "=r"(rank));
    const int cid = blockIdx.x >> 3;
    const int b0g = cid * 4;

    // ---- common preloads -------------------------------------------------------
    for (int i = tid; i < 4 * T_STEPS; i += NTHR) {
        int bb = i >> 9, tt = i & 511;
        sq[bb][tt] = g_seq[tt * BATCH + b0g + bb];
    }
    for (int i = tid; i < 2 * HID; i += NTHR) {
        int bb = i >> 8, U = i & 255;
        ((float*)&hbufA[0][U >> 1])[(U & 1) + 2 * bb] = h0[(b0g + bb) * HID + U];
        ((float*)&hbufB[0][U >> 1])[(U & 1) + 2 * bb] = h0[(b0g + 2 + bb) * HID + U];
    }
    if (tid < 8) { flagsA[tid] = 0; flagsB[tid] = 0; }

    const unsigned hbA_addr = smem_u32(&hbufA[0][0]);
    const unsigned hbB_addr = smem_u32(&hbufB[0][0]);
    const unsigned hlA_addr = smem_u32(&hlocA[0]);
    const unsigned hlB_addr = smem_u32(&hlocB[0]);
    const unsigned flA_addr = smem_u32(&flagsA[0]);
    const unsigned flB_addr = smem_u32(&flagsB[0]);

    if (tid < 256) {
        // ======================= GEMV role (warps 0-7) ==========================
        const int l  = tid & 127;           // gate row (broadcast-preserving map)
        const int kh = tid >> 7;            // k-half
        const int grow = (l >> 5) * HID + (int)rank * 32 + (l & 31);
        const bool isg = ((l >> 5) == 2);   // g-gate -> tanh

        ull w[64];
        const ull* wrow = reinterpret_cast<const ull*>(Whh) + (size_t)grow * 128 + kh * 64;
#pragma unroll
        for (int j = 0; j < 64; j++) w[j] = wrow[j];

        const float bsum = bih[grow] + bhh[grow];
        const float wih  = Wih[grow];

        __syncthreads();
        asm volatile("barrier.cluster.arrive.aligned;" ::: "memory");
        asm volatile("barrier.cluster.wait.aligned;"   ::: "memory");

        for (int t = 0; t < T_STEPS; t++) {
            const int ph = t & 1;
            const unsigned tgt = (unsigned)t;

            // ------------- group A -------------
            poll_flags(flA_addr, tgt);
            {
                const ulonglong2* hp = reinterpret_cast<const ulonglong2*>(&hbufA[ph][kh * 64]);
                float s0, s1;
                gemv128(hp, w, s0, s1);
                psumA[ph][kh][l][0] = s0;
                psumA[ph][kh][l][1] = s1;
            }
            asm volatile("bar.sync %0, %1;" :: "r"(5 + ph), "r"(256) : "memory");
            {
                float s = psumA[ph][0][l][kh] + psumA[ph][1][l][kh]
                        + bsum + wih * sq[kh][t];
                actA[ph][l][kh] = isg ? ftanh(s) : fsigmoid(s);
            }
            asm volatile("bar.arrive %0, %1;" :: "r"(1 + ph), "r"(NACT) : "memory");

            // ------------- group B -------------
            poll_flags(flB_addr, tgt);
            {
                const ulonglong2* hp = reinterpret_cast<const ulonglong2*>(&hbufB[ph][kh * 64]);
                float s0, s1;
                gemv128(hp, w, s0, s1);
                psumB[ph][kh][l][0] = s0;
                psumB[ph][kh][l][1] = s1;
            }
            asm volatile("bar.sync %0, %1;" :: "r"(7 + ph), "r"(256) : "memory");
            {
                float s = psumB[ph][0][l][kh] + psumB[ph][1][l][kh]
                        + bsum + wih * sq[2 + kh][t];
                actB[ph][l][kh] = isg ? ftanh(s) : fsigmoid(s);
            }
            asm volatile("bar.arrive %0, %1;" :: "r"(3 + ph), "r"(NACT) : "memory");
        }
    } else if (tid < 288) {
        // ======================= group-A updater (warp 8) =======================
        const int lane = tid - 256;                 // unit within this CTA
        const int U = (int)rank * 32 + lane;

        float cA0 = c0[(b0g + 0) * HID + U];
        float cA1 = c0[(b0g + 1) * HID + U];

        unsigned dstA0 = 0, dstA1 = 0, dfA = 0;
        if (lane < 8) {
            unsigned blk = (unsigned)rank * 256u;   // 16 float4 block
            asm("mapa.shared::cluster.u32 %0, %1, %2;" : "=r"(dstA0) : "r"(hbA_addr + blk),          "r"(lane));
            asm("mapa.shared::cluster.u32 %0, %1, %2;" : "=r"(dstA1) : "r"(hbA_addr + 2048u + blk),  "r"(lane));
            asm("mapa.shared::cluster.u32 %0, %1, %2;" : "=r"(dfA)   : "r"(flA_addr + 4u * rank),    "r"(lane));
        }

        __syncthreads();
        asm volatile("barrier.cluster.arrive.aligned;" ::: "memory");
        asm volatile("barrier.cluster.wait.aligned;"   ::: "memory");

        for (int t = 0; t < T_STEPS; t++) {
            const int ph = t & 1, nph = ph ^ 1;

            asm volatile("bar.sync %0, %1;" :: "r"(1 + ph), "r"(NACT) : "memory");
            float hA0, hA1;
            {
                float ai0 = actA[ph][lane][0],      af0 = actA[ph][32 + lane][0];
                float ag0 = actA[ph][64 + lane][0], ao0 = actA[ph][96 + lane][0];
                float ai1 = actA[ph][lane][1],      af1 = actA[ph][32 + lane][1];
                float ag1 = actA[ph][64 + lane][1], ao1 = actA[ph][96 + lane][1];
                cA0 = af0 * cA0 + ai0 * ag0;
                cA1 = af1 * cA1 + ai1 * ag1;
                hA0 = ao0 * ftanh(cA0);
                hA1 = ao1 * ftanh(cA1);
                ((float*)&hlocA[lane >> 1])[(lane & 1)]     = hA0;
                ((float*)&hlocA[lane >> 1])[(lane & 1) + 2] = hA1;
            }
            __syncwarp();
            if (lane < 8) {
                unsigned dst = nph ? dstA1 : dstA0;
#pragma unroll
                for (int j = 0; j < 16; j++) {
                    unsigned r0, r1, r2, r3;
                    asm volatile("ld.shared.v4.b32 {%0,%1,%2,%3}, [%4];"
                                 : "=r"(r0), "=r"(r1), "=r"(r2), "=r"(r3)
                                 : "r"(hlA_addr + 16u * j));
                    asm volatile("st.shared::cluster.v4.b32 [%0], {%1,%2,%3,%4};"
                                 :: "r"(dst + 16u * j), "r"(r0), "r"(r1), "r"(r2), "r"(r3)
                                 : "memory");
                }
                asm volatile("st.release.cluster.shared::cluster.u32 [%0], %1;"
                             :: "r"(dfA), "r"((unsigned)(t + 1)) : "memory");
            }
            g_hs[((size_t)t * BATCH + b0g + 0) * HID + U] = hA0;
            g_hs[((size_t)t * BATCH + b0g + 1) * HID + U] = hA1;
            __syncwarp();
        }
    } else {
        // ======================= group-B updater (warp 9) =======================
        const int lane = tid - 288;                 // unit within this CTA
        const int U = (int)rank * 32 + lane;

        float cB0 = c0[(b0g + 2) * HID + U];
        float cB1 = c0[(b0g + 3) * HID + U];

        unsigned dstB0 = 0, dstB1 = 0, dfB = 0;
        if (lane < 8) {
            unsigned blk = (unsigned)rank * 256u;
            asm("mapa.shared::cluster.u32 %0, %1, %2;" : "=r"(dstB0) : "r"(hbB_addr + blk),          "r"(lane));
            asm("mapa.shared::cluster.u32 %0, %1, %2;" : "=r"(dstB1) : "r"(hbB_addr + 2048u + blk),  "r"(lane));
            asm("mapa.shared::cluster.u32 %0, %1, %2;" : "=r"(dfB)   : "r"(flB_addr + 4u * rank),    "r"(lane));
        }

        __syncthreads();
        asm volatile("barrier.cluster.arrive.aligned;" ::: "memory");
        asm volatile("barrier.cluster.wait.aligned;"   ::: "memory");

        for (int t = 0; t < T_STEPS; t++) {
            const int ph = t & 1, nph = ph ^ 1;

            asm volatile("bar.sync %0, %1;" :: "r"(3 + ph), "r"(NACT) : "memory");
            float hB0, hB1;
            {
                float ai0 = actB[ph][lane][0],      af0 = actB[ph][32 + lane][0];
                float ag0 = actB[ph][64 + lane][0], ao0 = actB[ph][96 + lane][0];
                float ai1 = actB[ph][lane][1],      af1 = actB[ph][32 + lane][1];
                float ag1 = actB[ph][64 + lane][1], ao1 = actB[ph][96 + lane][1];
                cB0 = af0 * cB0 + ai0 * ag0;
                cB1 = af1 * cB1 + ai1 * ag1;
                hB0 = ao0 * ftanh(cB0);
                hB1 = ao1 * ftanh(cB1);
                ((float*)&hlocB[lane >> 1])[(lane & 1)]     = hB0;
                ((float*)&hlocB[lane >> 1])[(lane & 1) + 2] = hB1;
            }
            __syncwarp();
            if (lane < 8) {
                unsigned dst = nph ? dstB1 : dstB0;
#pragma unroll
                for (int j = 0; j < 16; j++) {
                    unsigned r0, r1, r2, r3;
                    asm volatile("ld.shared.v4.b32 {%0,%1,%2,%3}, [%4];"
                                 : "=r"(r0), "=r"(r1), "=r"(r2), "=r"(r3)
                                 : "r"(hlB_addr + 16u * j));
                    asm volatile("st.shared::cluster.v4.b32 [%0], {%1,%2,%3,%4};"
                                 :: "r"(dst + 16u * j), "r"(r0), "r"(r1), "r"(r2), "r"(r3)
                                 : "memory");
                }
                asm volatile("st.release.cluster.shared::cluster.u32 [%0], %1;"
                             :: "r"(dfB), "r"((unsigned)(t + 1)) : "memory");
            }
            g_hs[((size_t)t * BATCH + b0g + 2) * HID + U] = hB0;
            g_hs[((size_t)t * BATCH + b0g + 3) * HID + U] = hB1;
            __syncwarp();
        }
    }

    // keep smem alive until all peers' in-flight remote stores complete
    asm volatile("barrier.cluster.arrive.aligned;" ::: "memory");
    asm volatile("barrier.cluster.wait.aligned;"   ::: "memory");
}

// =============================================================================
// K3: AttLayer2 logits.  s2[t,b] = sum_a u2[a]*tanh( hs[t,b,:]@W2[:,a] + b2[a] )
// =============================================================================
__global__ __launch_bounds__(256) void k3_att2(const float* __restrict__ W2,
                                               const float* __restrict__ b2,
                                               const float* __restrict__ u2) {
    __shared__ float sh[128][33];
    __shared__ float sw[32][128];
    __shared__ float sp[128][17];
    __shared__ float sb2[A2N], su2[A2N];

    const int tid = threadIdx.x;
    const int b = blockIdx.x & 31, tq = blockIdx.x >> 5;
    const int t0 = tq * 128;
    if (tid < A2N) { sb2[tid] = b2[tid]; su2[tid] = u2[tid]; }

    const int tx = tid & 15;
    const int ty = tid >> 4;

    ull acc[8][4];
#pragma unroll
    for (int i = 0; i < 8; i++)
#pragma unroll
        for (int p = 0; p < 4; p++) acc[i][p] = 0ULL;

    for (int kc = 0; kc < 8; kc++) {
        __syncthreads();
        for (int idx = tid; idx < 4096; idx += 256) {
            int tl = idx >> 5, k = idx & 31;
            sh[tl][k] = g_hs[((size_t)(t0 + tl) * BATCH + b) * HID + kc * 32 + k];
        }
        for (int idx = tid; idx < 4096; idx += 256) {
            int k = idx >> 7, a = idx & 127;
            sw[k][a] = W2[(kc * 32 + k) * A2N + a];
        }
        __syncthreads();
#pragma unroll 4
        for (int k = 0; k < 32; k++) {
            const ull* wv = reinterpret_cast<const ull*>(&sw[k][tx * 8]);
            ull w0 = wv[0], w1 = wv[1], w2_ = wv[2], w3 = wv[3];
#pragma unroll
            for (int i = 0; i < 8; i++) {
                float hvv = sh[ty * 8 + i][k];
                ull hh;
                asm("mov.b64 %0, {%1,%1};" : "=l"(hh) : "f"(hvv));
                asm("fma.rn.f32x2 %0, %1, %2, %0;" : "+l"(acc[i][0]) : "l"(w0),  "l"(hh));
                asm("fma.rn.f32x2 %0, %1, %2, %0;" : "+l"(acc[i][1]) : "l"(w1),  "l"(hh));
                asm("fma.rn.f32x2 %0, %1, %2, %0;" : "+l"(acc[i][2]) : "l"(w2_), "l"(hh));
                asm("fma.rn.f32x2 %0, %1, %2, %0;" : "+l"(acc[i][3]) : "l"(w3),  "l"(hh));
            }
        }
    }
    float sres[8];
#pragma unroll
    for (int i = 0; i < 8; i++) sres[i] = 0.f;
#pragma unroll
    for (int i = 0; i < 8; i++) {
#pragma unroll
        for (int p = 0; p < 4; p++) {
            float lo, hi;
            asm("mov.b64 {%0,%1}, %2;" : "=f"(lo), "=f"(hi) : "l"(acc[i][p]));
            int a0 = tx * 8 + p * 2;
            sres[i] += su2[a0]     * tanhf(lo + sb2[a0]);
            sres[i] += su2[a0 + 1] * tanhf(hi + sb2[a0 + 1]);
        }
    }
#pragma unroll
    for (int i = 0; i < 8; i++) sp[ty * 8 + i][tx] = sres[i];
    __syncthreads();
    if (tid < 128) {
        float s = 0.f;
#pragma unroll
        for (int xx = 0; xx < 16; xx++) s += sp[tid][xx];
        g_s2[(t0 + tid) * BATCH + b] = s;
    }
}

// =============================================================================
// K4: softmax over T, attention pool, linear head.  One CTA per batch.
// =============================================================================
__global__ __launch_bounds__(256) void k4_final(const float* __restrict__ Wl,
                                                const float* __restrict__ bl,
                                                float* __restrict__ out) {
    __shared__ float a2s[T_STEPS];
    __shared__ float red[256];
    const int b = blockIdx.x, tid = threadIdx.x;

    for (int t = tid; t < T_STEPS; t += 256)
        a2s[t] = expf(g_s2[t * BATCH + b]);
    __syncthreads();

    float p = a2s[tid] + a2s[tid + 256];
    red[tid] = p;
    __syncthreads();
#pragma unroll
    for (int o = 128; o > 0; o >>= 1) {
        if (tid < o) red[tid] += red[tid + o];
        __syncthreads();
    }
    const float inv = 1.f / red[0];
    __syncthreads();

    float acc = 0.f;
    const float* hp = g_hs + (size_t)b * HID + tid;
#pragma unroll 8
    for (int t = 0; t < T_STEPS; t++)
        acc += a2s[t] * hp[(size_t)t * BATCH * HID];
    acc *= inv;

    float v = acc * Wl[tid];
    red[tid] = v;
    __syncthreads();
#pragma unroll
    for (int o = 128; o > 0; o >>= 1) {
        if (tid < o) red[tid] += red[tid + o];
        __syncthreads();
    }
    if (tid == 0) out[b] = red[0] + bl[0];
}

// =============================================================================
// launcher
// =============================================================================
extern "C" void kernel_launch(void* const* d_in, const int* in_sizes, int n_in,
                              void* d_out, int out_size) {
    const float* inputs = (const float*)d_in[0];
    const float* W1  = (const float*)d_in[1];
    const float* b1  = (const float*)d_in[2];
    const float* u1  = (const float*)d_in[3];
    const float* Wih = (const float*)d_in[4];
    const float* Whh = (const float*)d_in[5];
    const float* bih = (const float*)d_in[6];
    const float* bhh = (const float*)d_in[7];
    const float* h0  = (const float*)d_in[8];
    const float* c0  = (const float*)d_in[9];
    const float* W2  = (const float*)d_in[10];
    const float* b2  = (const float*)d_in[11];
    const float* u2  = (const float*)d_in[12];
    const float* Wl  = (const float*)d_in[13];
    const float* bl  = (const float*)d_in[14];
    float* out = (float*)d_out;

    k0_lut  <<<33, 256>>>(W1, b1, u1);
    k1_att1 <<<512, 256>>>(inputs);
    k_nop   <<<1, 32>>>();            // keeps ncu capture slot on k2
    k2_lstm <<<64, NTHR>>>(Whh, Wih, bih, bhh, h0, c0);
    k3_att2 <<<128, 256>>>(W2, b2, u2);
    k4_final<<<32, 256>>>(Wl, bl, out);
}